// round 5
// baseline (speedup 1.0000x reference)
#include <cuda_runtime.h>
#include <cuda_fp16.h>
#include <cstdint>
#include <math.h>

// Problem constants
#define TRI   32640      // 255 * 128, strict lower triangle count
#define EPAD  32768      // TRI padded to multiple of 256
#define NMAT  256
#define BATCH 1024
#define HIDW  1024
#define INW   256

// Device scratch (no allocations allowed). g_w2h padded rows are .bss zeros.
__device__ __half g_w2h[EPAD * HIDW];   // 67 MB, first TRI rows of W2 in fp16
__device__ __half g_xh [BATCH * INW];
__device__ __half g_w1h[HIDW * INW];
__device__ __half g_h  [BATCH * HIDW]; // softplus hidden, fp16

// ---------------- helpers ----------------
__device__ __forceinline__ uint32_t smem_u32(const void* p){
    uint32_t a;
    asm("{ .reg .u64 t; cvta.to.shared.u64 t, %1; cvt.u32.u64 %0, t; }" : "=r"(a) : "l"(p));
    return a;
}
__device__ __forceinline__ void cp16(uint32_t s, const void* g){
    asm volatile("cp.async.cg.shared.global [%0], [%1], 16;" :: "r"(s), "l"(g) : "memory");
}
#define CP_COMMIT() asm volatile("cp.async.commit_group;" ::: "memory")
#define CP_WAIT1()  asm volatile("cp.async.wait_group 1;" ::: "memory")
#define CP_WAIT2()  asm volatile("cp.async.wait_group 2;" ::: "memory")

__device__ __forceinline__ uint4 lds128(uint32_t base, int row, int t){
    uint32_t addr = base + (uint32_t)(row * 64 + t * 16);   // 64B rows, conflict-free
    uint4 v;
    asm volatile("ld.shared.v4.b32 {%0,%1,%2,%3}, [%4];"
                 : "=r"(v.x), "=r"(v.y), "=r"(v.z), "=r"(v.w) : "r"(addr));
    return v;
}
// fp16 MMA, fp32 accumulate. Logical k-order permuted (same perm on A and B).
__device__ __forceinline__ void mma16(float* d, uint32_t a0, uint32_t a1, uint32_t a2, uint32_t a3,
                                      uint32_t b0, uint32_t b1){
    asm volatile(
        "mma.sync.aligned.m16n8k16.row.col.f32.f16.f16.f32 "
        "{%0,%1,%2,%3}, {%4,%5,%6,%7}, {%8,%9}, {%0,%1,%2,%3};"
        : "+f"(d[0]), "+f"(d[1]), "+f"(d[2]), "+f"(d[3])
        : "r"(a0), "r"(a1), "r"(a2), "r"(a3), "r"(b0), "r"(b1));
}

// ==================== GEMM1: 128x128x32, 8 warps 4Mx2N, 2 CTA/SM ====================
static constexpr int G1_STAGE = (128 + 128) * 32 * 2;          // 16 KB
static constexpr int G1_SMEM  = 3 * G1_STAGE;                  // 48 KB

__global__ void __launch_bounds__(256, 2)
gemm1_f16(const float* __restrict__ bias)
{
    extern __shared__ char smem[];
    const uint32_t sbase = smem_u32(smem);
    const int tid  = threadIdx.x;
    const int lane = tid & 31;
    const int wid  = tid >> 5;
    const int wm   = wid & 3;
    const int wn   = wid >> 2;
    const int m0   = blockIdx.x * 128;
    const int n0   = blockIdx.y * 128;
    const int t    = lane & 3;
    const int g    = lane >> 2;
    const int K    = INW;            // 256

    auto load_stage = [&](int stage, int kt){
        const uint32_t sa = sbase + stage * G1_STAGE;
        const uint32_t sb = sa + 128 * 32 * 2;
        const __half* Ag = g_xh  + (size_t)m0 * K + kt * 32;
        const __half* Bg = g_w1h + (size_t)n0 * K + kt * 32;
        #pragma unroll
        for (int it = 0; it < 2; it++){
            int idx = tid + it * 256;
            int row = idx >> 2, ch = idx & 3;
            uint32_t soff = (uint32_t)(row * 64 + ch * 16);
            cp16(sa + soff, Ag + (size_t)row * K + ch * 8);
            cp16(sb + soff, Bg + (size_t)row * K + ch * 8);
        }
    };

    float acc[2][8][4];
    #pragma unroll
    for (int mf = 0; mf < 2; mf++)
        #pragma unroll
        for (int nf = 0; nf < 8; nf++)
            #pragma unroll
            for (int q = 0; q < 4; q++) acc[mf][nf][q] = 0.0f;

    load_stage(0, 0); CP_COMMIT();
    load_stage(1, 1); CP_COMMIT();

    const int KT = K >> 5;
    for (int kt = 0; kt < KT; kt++){
        CP_WAIT1();
        __syncthreads();
        if (kt + 2 < KT) load_stage((kt + 2) % 3, kt + 2);
        CP_COMMIT();

        const uint32_t sa = sbase + (kt % 3) * G1_STAGE;
        const uint32_t sb = sa + 128 * 32 * 2;

        uint4 a_lo[2], a_hi[2];
        #pragma unroll
        for (int mf = 0; mf < 2; mf++){
            int r = wm * 32 + mf * 16 + g;
            a_lo[mf] = lds128(sa, r,     t);
            a_hi[mf] = lds128(sa, r + 8, t);
        }
        #pragma unroll
        for (int ng = 0; ng < 2; ng++){
            uint4 Bv[4];
            #pragma unroll
            for (int nf = 0; nf < 4; nf++){
                int n = wn * 64 + (ng * 4 + nf) * 8 + g;
                Bv[nf] = lds128(sb, n, t);
            }
            #pragma unroll
            for (int mf = 0; mf < 2; mf++)
                #pragma unroll
                for (int nf = 0; nf < 4; nf++){
                    float* d = acc[mf][ng * 4 + nf];
                    mma16(d, a_lo[mf].x, a_hi[mf].x, a_lo[mf].y, a_hi[mf].y, Bv[nf].x, Bv[nf].y);
                    mma16(d, a_lo[mf].z, a_hi[mf].z, a_lo[mf].w, a_hi[mf].w, Bv[nf].z, Bv[nf].w);
                }
        }
    }

    // epilogue: softplus -> g_h (fp16)
    #pragma unroll
    for (int mf = 0; mf < 2; mf++){
        const int rbase = m0 + wm * 32 + mf * 16 + g;
        #pragma unroll
        for (int nf = 0; nf < 8; nf++){
            const int e0 = n0 + wn * 64 + nf * 8 + t * 2;
            const float bv0 = bias[e0], bv1 = bias[e0 + 1];
            __half* o0 = g_h + (size_t)rbase * HIDW + e0;
            __half* o8 = o0 + (size_t)8 * HIDW;
            float v0 = acc[mf][nf][0] + bv0, v1 = acc[mf][nf][1] + bv1;
            float v2 = acc[mf][nf][2] + bv0, v3 = acc[mf][nf][3] + bv1;
            v0 = fmaxf(v0, 0.0f) + log1pf(__expf(-fabsf(v0)));
            v1 = fmaxf(v1, 0.0f) + log1pf(__expf(-fabsf(v1)));
            v2 = fmaxf(v2, 0.0f) + log1pf(__expf(-fabsf(v2)));
            v3 = fmaxf(v3, 0.0f) + log1pf(__expf(-fabsf(v3)));
            *(__half2*)o0 = __floats2half2_rn(v0, v1);
            *(__half2*)o8 = __floats2half2_rn(v2, v3);
        }
    }
}

// ==================== GEMM2: 128x256x32, 8 warps 2Mx4N (warp tile 64x64) ====================
// 1 CTA/SM, 128 acc/thread. Minimizes smem bytes/MAC: 2(1/64+1/64).
static constexpr int G2_BM = 128, G2_BN = 256, G2_BK = 32, G2_STAGES = 4;
static constexpr int G2_ABYTES = G2_BM * G2_BK * 2;            // 8 KB
static constexpr int G2_STAGE  = (G2_BM + G2_BN) * G2_BK * 2;  // 24 KB
static constexpr int G2_SMEM   = G2_STAGES * G2_STAGE;         // 96 KB

__global__ void __launch_bounds__(256, 1)
gemm2_f16(const float* __restrict__ bias, float* __restrict__ O_)
{
    extern __shared__ char smem[];
    const uint32_t sbase = smem_u32(smem);
    const int tid  = threadIdx.x;
    const int lane = tid & 31;
    const int wid  = tid >> 5;
    const int wm   = wid & 1;        // 2 warps along M (64 rows each)
    const int wn   = wid >> 1;       // 4 warps along N (64 cols each)
    const int m0   = blockIdx.x * G2_BM;
    const int n0   = blockIdx.y * G2_BN;
    const int t    = lane & 3;
    const int g    = lane >> 2;
    const int K    = HIDW;           // 1024

    auto load_stage = [&](int stage, int kt){
        const uint32_t sa = sbase + stage * G2_STAGE;
        const uint32_t sb = sa + G2_ABYTES;
        const __half* Ag = g_h   + (size_t)m0 * K + kt * G2_BK;
        const __half* Bg = g_w2h + (size_t)n0 * K + kt * G2_BK;
        #pragma unroll
        for (int it = 0; it < 2; it++){            // A: 512 chunks
            int idx = tid + it * 256;
            int row = idx >> 2, ch = idx & 3;
            cp16(sa + (uint32_t)(row * 64 + ch * 16), Ag + (size_t)row * K + ch * 8);
        }
        #pragma unroll
        for (int it = 0; it < 4; it++){            // B: 1024 chunks
            int idx = tid + it * 256;
            int row = idx >> 2, ch = idx & 3;
            cp16(sb + (uint32_t)(row * 64 + ch * 16), Bg + (size_t)row * K + ch * 8);
        }
    };

    float acc[4][8][4];
    #pragma unroll
    for (int mf = 0; mf < 4; mf++)
        #pragma unroll
        for (int nf = 0; nf < 8; nf++)
            #pragma unroll
            for (int q = 0; q < 4; q++) acc[mf][nf][q] = 0.0f;

    load_stage(0, 0); CP_COMMIT();
    load_stage(1, 1); CP_COMMIT();
    load_stage(2, 2); CP_COMMIT();

    const int KT = K / G2_BK;        // 32
    for (int kt = 0; kt < KT; kt++){
        CP_WAIT2();
        __syncthreads();
        if (kt + 3 < KT) load_stage((kt + 3) % G2_STAGES, kt + 3);
        CP_COMMIT();

        const uint32_t sa = sbase + (kt % G2_STAGES) * G2_STAGE;
        const uint32_t sb = sa + G2_ABYTES;

        uint4 a_lo[4], a_hi[4];
        #pragma unroll
        for (int mf = 0; mf < 4; mf++){
            int r = wm * 64 + mf * 16 + g;
            a_lo[mf] = lds128(sa, r,     t);
            a_hi[mf] = lds128(sa, r + 8, t);
        }
        #pragma unroll
        for (int nf = 0; nf < 8; nf++){
            uint4 Bv = lds128(sb, wn * 64 + nf * 8 + g, t);
            #pragma unroll
            for (int mf = 0; mf < 4; mf++){
                float* d = acc[mf][nf];
                mma16(d, a_lo[mf].x, a_hi[mf].x, a_lo[mf].y, a_hi[mf].y, Bv.x, Bv.y);
                mma16(d, a_lo[mf].z, a_hi[mf].z, a_lo[mf].w, a_hi[mf].w, Bv.z, Bv.w);
            }
        }
    }

    // epilogue: scatter e -> (i,j) strict lower triangle, guard e < TRI
    #pragma unroll
    for (int mf = 0; mf < 4; mf++){
        const int rbase = m0 + wm * 64 + mf * 16 + g;
        #pragma unroll
        for (int nf = 0; nf < 8; nf++){
            const int e0 = n0 + wn * 64 + nf * 8 + t * 2;
            if (e0 >= TRI) continue;
            const float bv0 = bias[e0], bv1 = bias[e0 + 1];
            // e -> (i,j): i(i-1)/2 <= e < i(i+1)/2 ; j = e - i(i-1)/2
            int i = (int)((1.0f + sqrtf(8.0f * (float)e0 + 1.0f)) * 0.5f);
            while (i * (i - 1) / 2 > e0) i--;
            while ((i + 1) * i / 2 <= e0) i++;
            int j = e0 - i * (i - 1) / 2;
            int i1 = i, j1 = j + 1;
            if (j1 >= i1){ i1 = i + 1; j1 = 0; }
            float* o0 = O_ + (size_t)rbase * (NMAT * NMAT);
            float* o8 = o0 + (size_t)8 * (NMAT * NMAT);
            o0[i  * NMAT + j ] = acc[mf][nf][0] + bv0;
            o8[i  * NMAT + j ] = acc[mf][nf][2] + bv0;
            if (e0 + 1 < TRI){
                o0[i1 * NMAT + j1] = acc[mf][nf][1] + bv1;
                o8[i1 * NMAT + j1] = acc[mf][nf][3] + bv1;
            }
        }
    }
}

// -------------------------------------------------------------------------
// fp32 -> fp16 conversion. dst: 0 -> g_w2h, 1 -> g_xh, 2 -> g_w1h
// -------------------------------------------------------------------------
__global__ void __launch_bounds__(256) conv_half_k(const float4* __restrict__ in, int n4, int dst)
{
    int i = blockIdx.x * 256 + threadIdx.x;
    if (i >= n4) return;
    float4 v = in[i];
    __half2 h0 = __floats2half2_rn(v.x, v.y);
    __half2 h1 = __floats2half2_rn(v.z, v.w);
    uint2 w;
    w.x = *(uint32_t*)&h0;
    w.y = *(uint32_t*)&h1;
    __half* out = (dst == 0) ? g_w2h : (dst == 1) ? g_xh : g_w1h;
    ((uint2*)out)[i] = w;
}

// -------------------------------------------------------------------------
// Antisymmetrize: upper triangle = -lower^T, diagonal = 0. Tiled 32x32.
// -------------------------------------------------------------------------
__global__ void __launch_bounds__(256) antisym_kernel(float* __restrict__ out)
{
    __shared__ float s[32][33];
    const int b  = blockIdx.x;
    const int pr = blockIdx.y;
    int ti = 0;
    while ((ti + 1) * (ti + 2) / 2 <= pr) ti++;
    const int tj = pr - ti * (ti + 1) / 2;
    const int tx = threadIdx.x & 31, ty = threadIdx.x >> 5;  // 32 x 8
    float* base = out + (size_t)b * (NMAT * NMAT);

    #pragma unroll
    for (int yy = 0; yy < 4; yy++){
        int r = ty + yy * 8;
        s[r][tx] = base[(size_t)(ti * 32 + r) * NMAT + tj * 32 + tx];
    }
    __syncthreads();
    if (ti != tj){
        #pragma unroll
        for (int yy = 0; yy < 4; yy++){
            int r = ty + yy * 8;
            base[(size_t)(tj * 32 + r) * NMAT + ti * 32 + tx] = -s[tx][r];
        }
    } else {
        #pragma unroll
        for (int yy = 0; yy < 4; yy++){
            int r = ty + yy * 8;
            if (tx > r)
                base[(size_t)(ti * 32 + r) * NMAT + ti * 32 + tx] = -s[tx][r];
            else if (tx == r)
                base[(size_t)(ti * 32 + r) * NMAT + ti * 32 + tx] = 0.0f;
        }
    }
}

// -------------------------------------------------------------------------
extern "C" void kernel_launch(void* const* d_in, const int* in_sizes, int n_in,
                              void* d_out, int out_size)
{
    const float* x  = (const float*)d_in[0];   // [1024, 256]
    const float* W1 = (const float*)d_in[1];   // [1024, 256]
    const float* b1 = (const float*)d_in[2];   // [1024]
    const float* W2 = (const float*)d_in[3];   // [32896, 1024]
    const float* b2 = (const float*)d_in[4];   // [32896]
    float* out = (float*)d_out;                // [1024, 256, 256]

    cudaFuncSetAttribute(gemm1_f16, cudaFuncAttributeMaxDynamicSharedMemorySize, G1_SMEM);
    cudaFuncSetAttribute(gemm2_f16, cudaFuncAttributeMaxDynamicSharedMemorySize, G2_SMEM);

    // Convert operands to fp16 in device scratch (rows TRI..EPAD of g_w2h stay zero)
    conv_half_k<<<(TRI * HIDW / 4 + 255) / 256, 256>>>((const float4*)W2, TRI * HIDW / 4, 0);
    conv_half_k<<<(BATCH * INW / 4 + 255) / 256, 256>>>((const float4*)x,  BATCH * INW / 4, 1);
    conv_half_k<<<(HIDW * INW / 4 + 255) / 256, 256>>>((const float4*)W1, HIDW * INW / 4, 2);

    // GEMM1: h = softplus(x @ W1^T + b1) -> g_h (fp16)   (M=1024, N=1024, K=256)
    gemm1_f16<<<dim3(8, 8), 256, G1_SMEM>>>(b1);
    // GEMM2: elements = h @ W2^T + b2 -> strict lower triangle of out
    //        (M=1024, N=EPAD=128*256, K=1024)
    gemm2_f16<<<dim3(8, 128), 256, G2_SMEM>>>(b2, out);
    // Upper triangle = -lower^T, diagonal = 0
    antisym_kernel<<<dim3(1024, 36), 256>>>(out);
}

// round 6
// speedup vs baseline: 1.0522x; 1.0522x over previous
#include <cuda_runtime.h>
#include <cuda_fp16.h>
#include <cstdint>
#include <math.h>

// Problem constants
#define TRI   32640      // 255 * 128, strict lower triangle count
#define NMAT  256
#define BATCH 1024
#define HIDW  1024
#define INW   256

// Device scratch (no allocations allowed)
__device__ __half g_xh [BATCH * INW];   // x in fp16
__device__ __half g_w1h[HIDW * INW];    // W1 in fp16
__device__ __half g_h  [BATCH * HIDW];  // softplus hidden, fp16

// ---------------- helpers ----------------
__device__ __forceinline__ uint32_t smem_u32(const void* p){
    uint32_t a;
    asm("{ .reg .u64 t; cvta.to.shared.u64 t, %1; cvt.u32.u64 %0, t; }" : "=r"(a) : "l"(p));
    return a;
}
__device__ __forceinline__ void cp16(uint32_t s, const void* g){
    asm volatile("cp.async.cg.shared.global [%0], [%1], 16;" :: "r"(s), "l"(g) : "memory");
}
#define CP_COMMIT() asm volatile("cp.async.commit_group;" ::: "memory")
#define CP_WAIT1()  asm volatile("cp.async.wait_group 1;" ::: "memory")

__device__ __forceinline__ uint4 lds128(uint32_t addr){
    uint4 v;
    asm volatile("ld.shared.v4.b32 {%0,%1,%2,%3}, [%4];"
                 : "=r"(v.x), "=r"(v.y), "=r"(v.z), "=r"(v.w) : "r"(addr));
    return v;
}
__device__ __forceinline__ float4 lds128f(uint32_t addr){
    float4 v;
    asm volatile("ld.shared.v4.f32 {%0,%1,%2,%3}, [%4];"
                 : "=f"(v.x), "=f"(v.y), "=f"(v.z), "=f"(v.w) : "r"(addr));
    return v;
}
__device__ __forceinline__ uint32_t packh2(float a, float b){
    __half2 h = __floats2half2_rn(a, b);
    return *(uint32_t*)&h;
}
// fp16 MMA, fp32 accumulate. Logical k-order permuted (same perm on A and B).
__device__ __forceinline__ void mma16(float* d, uint32_t a0, uint32_t a1, uint32_t a2, uint32_t a3,
                                      uint32_t b0, uint32_t b1){
    asm volatile(
        "mma.sync.aligned.m16n8k16.row.col.f32.f16.f16.f32 "
        "{%0,%1,%2,%3}, {%4,%5,%6,%7}, {%8,%9}, {%0,%1,%2,%3};"
        : "+f"(d[0]), "+f"(d[1]), "+f"(d[2]), "+f"(d[3])
        : "r"(a0), "r"(a1), "r"(a2), "r"(a3), "r"(b0), "r"(b1));
}

// ==================== GEMM1: 128x128x32, 8 warps 4Mx2N, 2 CTA/SM ====================
static constexpr int G1_STAGE = (128 + 128) * 32 * 2;          // 16 KB
static constexpr int G1_SMEM  = 3 * G1_STAGE;                  // 48 KB

__global__ void __launch_bounds__(256, 2)
gemm1_f16(const float* __restrict__ bias)
{
    extern __shared__ char smem[];
    const uint32_t sbase = smem_u32(smem);
    const int tid  = threadIdx.x;
    const int lane = tid & 31;
    const int wid  = tid >> 5;
    const int wm   = wid & 3;
    const int wn   = wid >> 2;
    const int m0   = blockIdx.x * 128;
    const int n0   = blockIdx.y * 128;
    const int t    = lane & 3;
    const int g    = lane >> 2;
    const int K    = INW;            // 256

    auto load_stage = [&](int stage, int kt){
        const uint32_t sa = sbase + stage * G1_STAGE;
        const uint32_t sb = sa + 128 * 32 * 2;
        const __half* Ag = g_xh  + (size_t)m0 * K + kt * 32;
        const __half* Bg = g_w1h + (size_t)n0 * K + kt * 32;
        #pragma unroll
        for (int it = 0; it < 2; it++){
            int idx = tid + it * 256;
            int row = idx >> 2, ch = idx & 3;
            uint32_t soff = (uint32_t)(row * 64 + ch * 16);
            cp16(sa + soff, Ag + (size_t)row * K + ch * 8);
            cp16(sb + soff, Bg + (size_t)row * K + ch * 8);
        }
    };

    float acc[2][8][4];
    #pragma unroll
    for (int mf = 0; mf < 2; mf++)
        #pragma unroll
        for (int nf = 0; nf < 8; nf++)
            #pragma unroll
            for (int q = 0; q < 4; q++) acc[mf][nf][q] = 0.0f;

    load_stage(0, 0); CP_COMMIT();
    load_stage(1, 1); CP_COMMIT();

    const int KT = K >> 5;
    for (int kt = 0; kt < KT; kt++){
        CP_WAIT1();
        __syncthreads();
        if (kt + 2 < KT) load_stage((kt + 2) % 3, kt + 2);
        CP_COMMIT();

        const uint32_t sa = sbase + (kt % 3) * G1_STAGE;
        const uint32_t sb = sa + 128 * 32 * 2;

        uint4 a_lo[2], a_hi[2];
        #pragma unroll
        for (int mf = 0; mf < 2; mf++){
            int r = wm * 32 + mf * 16 + g;
            a_lo[mf] = lds128(sa + (uint32_t)(r * 64 + t * 16));
            a_hi[mf] = lds128(sa + (uint32_t)((r + 8) * 64 + t * 16));
        }
        #pragma unroll
        for (int ng = 0; ng < 2; ng++){
            uint4 Bv[4];
            #pragma unroll
            for (int nf = 0; nf < 4; nf++){
                int n = wn * 64 + (ng * 4 + nf) * 8 + g;
                Bv[nf] = lds128(sb + (uint32_t)(n * 64 + t * 16));
            }
            #pragma unroll
            for (int mf = 0; mf < 2; mf++)
                #pragma unroll
                for (int nf = 0; nf < 4; nf++){
                    float* d = acc[mf][ng * 4 + nf];
                    mma16(d, a_lo[mf].x, a_hi[mf].x, a_lo[mf].y, a_hi[mf].y, Bv[nf].x, Bv[nf].y);
                    mma16(d, a_lo[mf].z, a_hi[mf].z, a_lo[mf].w, a_hi[mf].w, Bv[nf].z, Bv[nf].w);
                }
        }
    }

    // epilogue: softplus -> g_h (fp16)
    #pragma unroll
    for (int mf = 0; mf < 2; mf++){
        const int rbase = m0 + wm * 32 + mf * 16 + g;
        #pragma unroll
        for (int nf = 0; nf < 8; nf++){
            const int e0 = n0 + wn * 64 + nf * 8 + t * 2;
            const float bv0 = bias[e0], bv1 = bias[e0 + 1];
            __half* o0 = g_h + (size_t)rbase * HIDW + e0;
            __half* o8 = o0 + (size_t)8 * HIDW;
            float v0 = acc[mf][nf][0] + bv0, v1 = acc[mf][nf][1] + bv1;
            float v2 = acc[mf][nf][2] + bv0, v3 = acc[mf][nf][3] + bv1;
            v0 = fmaxf(v0, 0.0f) + log1pf(__expf(-fabsf(v0)));
            v1 = fmaxf(v1, 0.0f) + log1pf(__expf(-fabsf(v1)));
            v2 = fmaxf(v2, 0.0f) + log1pf(__expf(-fabsf(v2)));
            v3 = fmaxf(v3, 0.0f) + log1pf(__expf(-fabsf(v3)));
            *(__half2*)o0 = __floats2half2_rn(v0, v1);
            *(__half2*)o8 = __floats2half2_rn(v2, v3);
        }
    }
}

// ==================== GEMM2: 128x128x32, warp tile 32x64, 2 CTA/SM ====================
// A = g_h (fp16, cp.async). B = W2 read DIRECTLY as fp32 (cp.async, 144B row
// stride for conflict-free fp32 fragment LDS), converted to fp16 in registers.
static constexpr int G2_ASZ   = 128 * 32 * 2;      // 8 KB
static constexpr int G2_BSTR  = 144;               // fp32 row stride (bank-rotating)
static constexpr int G2_BSZ   = 128 * G2_BSTR;     // 18 KB
static constexpr int G2_STAGE = G2_ASZ + G2_BSZ;   // 26624 B
static constexpr int G2_SMEM  = 3 * G2_STAGE;      // 79872 B

__global__ void __launch_bounds__(256, 2)
gemm2_f16(const float* __restrict__ W2, const float* __restrict__ bias, float* __restrict__ O_)
{
    extern __shared__ char smem[];
    const uint32_t sbase = smem_u32(smem);
    const int tid  = threadIdx.x;
    const int lane = tid & 31;
    const int wid  = tid >> 5;
    const int wm   = wid & 3;        // 4 warps along M (32 rows each)
    const int wn   = wid >> 2;       // 2 warps along N (64 cols each)
    const int m0   = blockIdx.x * 128;
    const int n0   = blockIdx.y * 128;
    const int t    = lane & 3;
    const int g    = lane >> 2;
    const int K    = HIDW;           // 1024

    auto load_stage = [&](int stage, int kt){
        const uint32_t sa = sbase + stage * G2_STAGE;
        const uint32_t sb = sa + G2_ASZ;
        const __half* Ag = g_h + (size_t)m0 * K + kt * 32;
        const float*  Bg = W2  + (size_t)n0 * K + kt * 32;
        #pragma unroll
        for (int it = 0; it < 2; it++){            // A: 512 16B chunks
            int idx = tid + it * 256;
            int row = idx >> 2, ch = idx & 3;
            cp16(sa + (uint32_t)(row * 64 + ch * 16), Ag + (size_t)row * K + ch * 8);
        }
        #pragma unroll
        for (int it = 0; it < 4; it++){            // B: 1024 16B chunks (fp32)
            int idx = tid + it * 256;
            int row = idx >> 3, ch = idx & 7;
            cp16(sb + (uint32_t)(row * G2_BSTR + ch * 16), Bg + (size_t)row * K + ch * 4);
        }
    };

    float acc[2][8][4];
    #pragma unroll
    for (int mf = 0; mf < 2; mf++)
        #pragma unroll
        for (int nf = 0; nf < 8; nf++)
            #pragma unroll
            for (int q = 0; q < 4; q++) acc[mf][nf][q] = 0.0f;

    load_stage(0, 0); CP_COMMIT();
    load_stage(1, 1); CP_COMMIT();

    const int KT = K >> 5;           // 32
    for (int kt = 0; kt < KT; kt++){
        CP_WAIT1();
        __syncthreads();
        if (kt + 2 < KT) load_stage((kt + 2) % 3, kt + 2);
        CP_COMMIT();

        const uint32_t sa = sbase + (kt % 3) * G2_STAGE;
        const uint32_t sb = sa + G2_ASZ;

        uint4 a_lo[2], a_hi[2];
        #pragma unroll
        for (int mf = 0; mf < 2; mf++){
            int r = wm * 32 + mf * 16 + g;
            a_lo[mf] = lds128(sa + (uint32_t)(r * 64 + t * 16));
            a_hi[mf] = lds128(sa + (uint32_t)((r + 8) * 64 + t * 16));
        }
        #pragma unroll
        for (int ng = 0; ng < 2; ng++){
            uint4 Bv[4];
            #pragma unroll
            for (int nf = 0; nf < 4; nf++){
                int n = wn * 64 + (ng * 4 + nf) * 8 + g;
                uint32_t ba = sb + (uint32_t)(n * G2_BSTR + t * 32);
                float4 f0 = lds128f(ba);
                float4 f1 = lds128f(ba + 16);
                Bv[nf].x = packh2(f0.x, f0.y);
                Bv[nf].y = packh2(f0.z, f0.w);
                Bv[nf].z = packh2(f1.x, f1.y);
                Bv[nf].w = packh2(f1.z, f1.w);
            }
            #pragma unroll
            for (int mf = 0; mf < 2; mf++)
                #pragma unroll
                for (int nf = 0; nf < 4; nf++){
                    float* d = acc[mf][ng * 4 + nf];
                    mma16(d, a_lo[mf].x, a_hi[mf].x, a_lo[mf].y, a_hi[mf].y, Bv[nf].x, Bv[nf].y);
                    mma16(d, a_lo[mf].z, a_hi[mf].z, a_lo[mf].w, a_hi[mf].w, Bv[nf].z, Bv[nf].w);
                }
        }
    }

    // epilogue: scatter e -> (i,j) strict lower triangle (grid covers e < TRI exactly)
    #pragma unroll
    for (int mf = 0; mf < 2; mf++){
        const int rbase = m0 + wm * 32 + mf * 16 + g;
        #pragma unroll
        for (int nf = 0; nf < 8; nf++){
            const int e0 = n0 + wn * 64 + nf * 8 + t * 2;
            const float bv0 = bias[e0], bv1 = bias[e0 + 1];
            // e -> (i,j): i(i-1)/2 <= e < i(i+1)/2 ; j = e - i(i-1)/2
            int i = (int)((1.0f + sqrtf(8.0f * (float)e0 + 1.0f)) * 0.5f);
            while (i * (i - 1) / 2 > e0) i--;
            while ((i + 1) * i / 2 <= e0) i++;
            int j = e0 - i * (i - 1) / 2;
            int i1 = i, j1 = j + 1;
            if (j1 >= i1){ i1 = i + 1; j1 = 0; }
            float* o0 = O_ + (size_t)rbase * (NMAT * NMAT);
            float* o8 = o0 + (size_t)8 * (NMAT * NMAT);
            o0[i  * NMAT + j ] = acc[mf][nf][0] + bv0;
            o0[i1 * NMAT + j1] = acc[mf][nf][1] + bv1;
            o8[i  * NMAT + j ] = acc[mf][nf][2] + bv0;
            o8[i1 * NMAT + j1] = acc[mf][nf][3] + bv1;
        }
    }
}

// -------------------------------------------------------------------------
// fp32 -> fp16 conversion (small inputs only). dst: 1 -> g_xh, 2 -> g_w1h
// -------------------------------------------------------------------------
__global__ void __launch_bounds__(256) conv_half_k(const float4* __restrict__ in, int n4, int dst)
{
    int i = blockIdx.x * 256 + threadIdx.x;
    if (i >= n4) return;
    float4 v = in[i];
    uint2 w;
    w.x = packh2(v.x, v.y);
    w.y = packh2(v.z, v.w);
    __half* out = (dst == 1) ? g_xh : g_w1h;
    ((uint2*)out)[i] = w;
}

// -------------------------------------------------------------------------
// Antisymmetrize: upper triangle = -lower^T, diagonal = 0. Tiled 32x32.
// -------------------------------------------------------------------------
__global__ void __launch_bounds__(256) antisym_kernel(float* __restrict__ out)
{
    __shared__ float s[32][33];
    const int b  = blockIdx.x;
    const int pr = blockIdx.y;
    int ti = 0;
    while ((ti + 1) * (ti + 2) / 2 <= pr) ti++;
    const int tj = pr - ti * (ti + 1) / 2;
    const int tx = threadIdx.x & 31, ty = threadIdx.x >> 5;  // 32 x 8
    float* base = out + (size_t)b * (NMAT * NMAT);

    #pragma unroll
    for (int yy = 0; yy < 4; yy++){
        int r = ty + yy * 8;
        s[r][tx] = base[(size_t)(ti * 32 + r) * NMAT + tj * 32 + tx];
    }
    __syncthreads();
    if (ti != tj){
        #pragma unroll
        for (int yy = 0; yy < 4; yy++){
            int r = ty + yy * 8;
            base[(size_t)(tj * 32 + r) * NMAT + ti * 32 + tx] = -s[tx][r];
        }
    } else {
        #pragma unroll
        for (int yy = 0; yy < 4; yy++){
            int r = ty + yy * 8;
            if (tx > r)
                base[(size_t)(ti * 32 + r) * NMAT + ti * 32 + tx] = -s[tx][r];
            else if (tx == r)
                base[(size_t)(ti * 32 + r) * NMAT + ti * 32 + tx] = 0.0f;
        }
    }
}

// -------------------------------------------------------------------------
extern "C" void kernel_launch(void* const* d_in, const int* in_sizes, int n_in,
                              void* d_out, int out_size)
{
    const float* x  = (const float*)d_in[0];   // [1024, 256]
    const float* W1 = (const float*)d_in[1];   // [1024, 256]
    const float* b1 = (const float*)d_in[2];   // [1024]
    const float* W2 = (const float*)d_in[3];   // [32896, 1024]
    const float* b2 = (const float*)d_in[4];   // [32896]
    float* out = (float*)d_out;                // [1024, 256, 256]

    cudaFuncSetAttribute(gemm1_f16, cudaFuncAttributeMaxDynamicSharedMemorySize, G1_SMEM);
    cudaFuncSetAttribute(gemm2_f16, cudaFuncAttributeMaxDynamicSharedMemorySize, G2_SMEM);

    // Convert small operands to fp16 (W2 is consumed as fp32 by gemm2 directly)
    conv_half_k<<<(BATCH * INW / 4 + 255) / 256, 256>>>((const float4*)x,  BATCH * INW / 4, 1);
    conv_half_k<<<(HIDW * INW / 4 + 255) / 256, 256>>>((const float4*)W1, HIDW * INW / 4, 2);

    // GEMM1: h = softplus(x @ W1^T + b1) -> g_h (fp16)   (M=1024, N=1024, K=256)
    gemm1_f16<<<dim3(8, 8), 256, G1_SMEM>>>(b1);
    // GEMM2: elements = h @ W2^T + b2 -> strict lower triangle of out
    //        (M=1024, N=TRI=255*128, K=1024), W2 read as fp32, converted in-kernel
    gemm2_f16<<<dim3(8, 255), 256, G2_SMEM>>>(W2, b2, out);
    // Upper triangle = -lower^T, diagonal = 0
    antisym_kernel<<<dim3(1024, 36), 256>>>(out);
}

// round 7
// speedup vs baseline: 1.1654x; 1.1076x over previous
#include <cuda_runtime.h>
#include <cuda_fp16.h>
#include <cstdint>
#include <math.h>

// Problem constants
#define TRI   32640      // 255 * 128, strict lower triangle count
#define NMAT  256
#define BATCH 1024
#define HIDW  1024
#define INW   256

// Device scratch (no allocations allowed)
__device__ __half g_w2h[TRI * HIDW];    // 66.8 MB, first TRI rows of W2 in fp16
__device__ __half g_xh [BATCH * INW];   // x in fp16
__device__ __half g_w1h[HIDW * INW];    // W1 in fp16
__device__ __half g_h  [BATCH * HIDW];  // softplus hidden, fp16

// ---------------- helpers ----------------
__device__ __forceinline__ uint32_t smem_u32(const void* p){
    uint32_t a;
    asm("{ .reg .u64 t; cvta.to.shared.u64 t, %1; cvt.u32.u64 %0, t; }" : "=r"(a) : "l"(p));
    return a;
}
__device__ __forceinline__ void cp16(uint32_t s, const void* g){
    asm volatile("cp.async.cg.shared.global [%0], [%1], 16;" :: "r"(s), "l"(g) : "memory");
}
#define CP_COMMIT() asm volatile("cp.async.commit_group;" ::: "memory")
#define CP_WAIT1()  asm volatile("cp.async.wait_group 1;" ::: "memory")

__device__ __forceinline__ uint4 lds128(uint32_t addr){
    uint4 v;
    asm volatile("ld.shared.v4.b32 {%0,%1,%2,%3}, [%4];"
                 : "=r"(v.x), "=r"(v.y), "=r"(v.z), "=r"(v.w) : "r"(addr));
    return v;
}
__device__ __forceinline__ uint32_t packh2(float a, float b){
    __half2 h = __floats2half2_rn(a, b);
    return *(uint32_t*)&h;
}
// fp16 MMA, fp32 accumulate. Logical k-order permuted (same perm on A and B).
__device__ __forceinline__ void mma16(float* d, uint32_t a0, uint32_t a1, uint32_t a2, uint32_t a3,
                                      uint32_t b0, uint32_t b1){
    asm volatile(
        "mma.sync.aligned.m16n8k16.row.col.f32.f16.f16.f32 "
        "{%0,%1,%2,%3}, {%4,%5,%6,%7}, {%8,%9}, {%0,%1,%2,%3};"
        : "+f"(d[0]), "+f"(d[1]), "+f"(d[2]), "+f"(d[3])
        : "r"(a0), "r"(a1), "r"(a2), "r"(a3), "r"(b0), "r"(b1));
}

// ==================== GEMM1: 128x128x32, 8 warps 4Mx2N, 2 CTA/SM ====================
static constexpr int G1_STAGE = (128 + 128) * 32 * 2;          // 16 KB
static constexpr int G1_SMEM  = 3 * G1_STAGE;                  // 48 KB

__global__ void __launch_bounds__(256, 2)
gemm1_f16(const float* __restrict__ bias)
{
    extern __shared__ char smem[];
    const uint32_t sbase = smem_u32(smem);
    const int tid  = threadIdx.x;
    const int lane = tid & 31;
    const int wid  = tid >> 5;
    const int wm   = wid & 3;
    const int wn   = wid >> 2;
    const int m0   = blockIdx.x * 128;
    const int n0   = blockIdx.y * 128;
    const int t    = lane & 3;
    const int g    = lane >> 2;
    const int K    = INW;            // 256

    auto load_stage = [&](int stage, int kt){
        const uint32_t sa = sbase + stage * G1_STAGE;
        const uint32_t sb = sa + 128 * 32 * 2;
        const __half* Ag = g_xh  + (size_t)m0 * K + kt * 32;
        const __half* Bg = g_w1h + (size_t)n0 * K + kt * 32;
        #pragma unroll
        for (int it = 0; it < 2; it++){
            int idx = tid + it * 256;
            int row = idx >> 2, ch = idx & 3;
            uint32_t soff = (uint32_t)(row * 64 + ch * 16);
            cp16(sa + soff, Ag + (size_t)row * K + ch * 8);
            cp16(sb + soff, Bg + (size_t)row * K + ch * 8);
        }
    };

    float acc[2][8][4];
    #pragma unroll
    for (int mf = 0; mf < 2; mf++)
        #pragma unroll
        for (int nf = 0; nf < 8; nf++)
            #pragma unroll
            for (int q = 0; q < 4; q++) acc[mf][nf][q] = 0.0f;

    load_stage(0, 0); CP_COMMIT();
    load_stage(1, 1); CP_COMMIT();

    const int KT = K >> 5;
    for (int kt = 0; kt < KT; kt++){
        CP_WAIT1();
        __syncthreads();
        if (kt + 2 < KT) load_stage((kt + 2) % 3, kt + 2);
        CP_COMMIT();

        const uint32_t sa = sbase + (kt % 3) * G1_STAGE;
        const uint32_t sb = sa + 128 * 32 * 2;

        uint4 a_lo[2], a_hi[2];
        #pragma unroll
        for (int mf = 0; mf < 2; mf++){
            int r = wm * 32 + mf * 16 + g;
            a_lo[mf] = lds128(sa + (uint32_t)(r * 64 + t * 16));
            a_hi[mf] = lds128(sa + (uint32_t)((r + 8) * 64 + t * 16));
        }
        #pragma unroll
        for (int ng = 0; ng < 2; ng++){
            uint4 Bv[4];
            #pragma unroll
            for (int nf = 0; nf < 4; nf++){
                int n = wn * 64 + (ng * 4 + nf) * 8 + g;
                Bv[nf] = lds128(sb + (uint32_t)(n * 64 + t * 16));
            }
            #pragma unroll
            for (int mf = 0; mf < 2; mf++)
                #pragma unroll
                for (int nf = 0; nf < 4; nf++){
                    float* d = acc[mf][ng * 4 + nf];
                    mma16(d, a_lo[mf].x, a_hi[mf].x, a_lo[mf].y, a_hi[mf].y, Bv[nf].x, Bv[nf].y);
                    mma16(d, a_lo[mf].z, a_hi[mf].z, a_lo[mf].w, a_hi[mf].w, Bv[nf].z, Bv[nf].w);
                }
        }
    }

    // epilogue: softplus -> g_h (fp16)
    #pragma unroll
    for (int mf = 0; mf < 2; mf++){
        const int rbase = m0 + wm * 32 + mf * 16 + g;
        #pragma unroll
        for (int nf = 0; nf < 8; nf++){
            const int e0 = n0 + wn * 64 + nf * 8 + t * 2;
            const float bv0 = bias[e0], bv1 = bias[e0 + 1];
            __half* o0 = g_h + (size_t)rbase * HIDW + e0;
            __half* o8 = o0 + (size_t)8 * HIDW;
            float v0 = acc[mf][nf][0] + bv0, v1 = acc[mf][nf][1] + bv1;
            float v2 = acc[mf][nf][2] + bv0, v3 = acc[mf][nf][3] + bv1;
            v0 = fmaxf(v0, 0.0f) + log1pf(__expf(-fabsf(v0)));
            v1 = fmaxf(v1, 0.0f) + log1pf(__expf(-fabsf(v1)));
            v2 = fmaxf(v2, 0.0f) + log1pf(__expf(-fabsf(v2)));
            v3 = fmaxf(v3, 0.0f) + log1pf(__expf(-fabsf(v3)));
            *(__half2*)o0 = __floats2half2_rn(v0, v1);
            *(__half2*)o8 = __floats2half2_rn(v2, v3);
        }
    }
}

// ==================== GEMM2: 128x128x64, warp tile 32x64, 2 CTA/SM ====================
// fp16 A (g_h) and fp16 B (g_w2h pre-converted). BK=64 halves loop/barrier
// overhead vs BK=32. 128B rows need a 1-bit chunk swizzle (ch ^= (row&1)<<2)
// to keep both cp.async stores and LDS.128 fragment loads conflict-free.
static constexpr int G2_BK    = 64;
static constexpr int G2_ASZ   = 128 * G2_BK * 2;   // 16 KB
static constexpr int G2_STAGE = 2 * G2_ASZ;        // 32 KB (A + B)
static constexpr int G2_SMEM  = 3 * G2_STAGE;      // 96 KB

__device__ __forceinline__ uint32_t g2_off(int row, int ch){
    return (uint32_t)(row * 128 + ((ch ^ ((row & 1) << 2)) << 4));
}

__global__ void __launch_bounds__(256, 2)
gemm2_f16(const float* __restrict__ bias, float* __restrict__ O_)
{
    extern __shared__ char smem[];
    const uint32_t sbase = smem_u32(smem);
    const int tid  = threadIdx.x;
    const int lane = tid & 31;
    const int wid  = tid >> 5;
    const int wm   = wid & 3;        // 4 warps along M (32 rows each)
    const int wn   = wid >> 2;       // 2 warps along N (64 cols each)
    const int m0   = blockIdx.x * 128;
    const int n0   = blockIdx.y * 128;
    const int t    = lane & 3;
    const int g    = lane >> 2;
    const int K    = HIDW;           // 1024

    auto load_stage = [&](int stage, int kt){
        const uint32_t sa = sbase + stage * G2_STAGE;
        const uint32_t sb = sa + G2_ASZ;
        const __half* Ag = g_h   + (size_t)m0 * K + kt * G2_BK;
        const __half* Bg = g_w2h + (size_t)n0 * K + kt * G2_BK;
        #pragma unroll
        for (int it = 0; it < 4; it++){            // 1024 16B chunks per tile
            int idx = tid + it * 256;
            int row = idx >> 3, ch = idx & 7;
            uint32_t soff = g2_off(row, ch);
            cp16(sa + soff, Ag + (size_t)row * K + ch * 8);
            cp16(sb + soff, Bg + (size_t)row * K + ch * 8);
        }
    };

    float acc[2][8][4];
    #pragma unroll
    for (int mf = 0; mf < 2; mf++)
        #pragma unroll
        for (int nf = 0; nf < 8; nf++)
            #pragma unroll
            for (int q = 0; q < 4; q++) acc[mf][nf][q] = 0.0f;

    load_stage(0, 0); CP_COMMIT();
    load_stage(1, 1); CP_COMMIT();

    const int KT = K / G2_BK;        // 16
    for (int kt = 0; kt < KT; kt++){
        CP_WAIT1();
        __syncthreads();
        if (kt + 2 < KT) load_stage((kt + 2) % 3, kt + 2);
        CP_COMMIT();

        const uint32_t sa = sbase + (kt % 3) * G2_STAGE;
        const uint32_t sb = sa + G2_ASZ;

        #pragma unroll
        for (int kk = 0; kk < 2; kk++){            // two 32-k halves
            const int ch = kk * 4 + t;             // this thread's 16B chunk
            uint4 a_lo[2], a_hi[2];
            #pragma unroll
            for (int mf = 0; mf < 2; mf++){
                int r = wm * 32 + mf * 16 + g;
                a_lo[mf] = lds128(sa + g2_off(r,     ch));
                a_hi[mf] = lds128(sa + g2_off(r + 8, ch));
            }
            #pragma unroll
            for (int ng = 0; ng < 2; ng++){
                uint4 Bv[4];
                #pragma unroll
                for (int nf = 0; nf < 4; nf++){
                    int n = wn * 64 + (ng * 4 + nf) * 8 + g;
                    Bv[nf] = lds128(sb + g2_off(n, ch));
                }
                #pragma unroll
                for (int mf = 0; mf < 2; mf++)
                    #pragma unroll
                    for (int nf = 0; nf < 4; nf++){
                        float* d = acc[mf][ng * 4 + nf];
                        mma16(d, a_lo[mf].x, a_hi[mf].x, a_lo[mf].y, a_hi[mf].y, Bv[nf].x, Bv[nf].y);
                        mma16(d, a_lo[mf].z, a_hi[mf].z, a_lo[mf].w, a_hi[mf].w, Bv[nf].z, Bv[nf].w);
                    }
            }
        }
    }

    // epilogue: scatter e -> (i,j) strict lower triangle (grid covers e < TRI exactly)
    #pragma unroll
    for (int mf = 0; mf < 2; mf++){
        const int rbase = m0 + wm * 32 + mf * 16 + g;
        #pragma unroll
        for (int nf = 0; nf < 8; nf++){
            const int e0 = n0 + wn * 64 + nf * 8 + t * 2;
            const float bv0 = bias[e0], bv1 = bias[e0 + 1];
            // e -> (i,j): i(i-1)/2 <= e < i(i+1)/2 ; j = e - i(i-1)/2
            int i = (int)((1.0f + sqrtf(8.0f * (float)e0 + 1.0f)) * 0.5f);
            while (i * (i - 1) / 2 > e0) i--;
            while ((i + 1) * i / 2 <= e0) i++;
            int j = e0 - i * (i - 1) / 2;
            int i1 = i, j1 = j + 1;
            if (j1 >= i1){ i1 = i + 1; j1 = 0; }
            float* o0 = O_ + (size_t)rbase * (NMAT * NMAT);
            float* o8 = o0 + (size_t)8 * (NMAT * NMAT);
            o0[i  * NMAT + j ] = acc[mf][nf][0] + bv0;
            o0[i1 * NMAT + j1] = acc[mf][nf][1] + bv1;
            o8[i  * NMAT + j ] = acc[mf][nf][2] + bv0;
            o8[i1 * NMAT + j1] = acc[mf][nf][3] + bv1;
        }
    }
}

// -------------------------------------------------------------------------
// fp32 -> fp16 conversion. dst: 0 -> g_w2h, 1 -> g_xh, 2 -> g_w1h
// -------------------------------------------------------------------------
__global__ void __launch_bounds__(256) conv_half_k(const float4* __restrict__ in, int n4, int dst)
{
    int i = blockIdx.x * 256 + threadIdx.x;
    if (i >= n4) return;
    float4 v = in[i];
    uint2 w;
    w.x = packh2(v.x, v.y);
    w.y = packh2(v.z, v.w);
    __half* out = (dst == 0) ? g_w2h : (dst == 1) ? g_xh : g_w1h;
    ((uint2*)out)[i] = w;
}

// -------------------------------------------------------------------------
// Antisymmetrize: upper triangle = -lower^T, diagonal = 0. Tiled 32x32.
// -------------------------------------------------------------------------
__global__ void __launch_bounds__(256) antisym_kernel(float* __restrict__ out)
{
    __shared__ float s[32][33];
    const int b  = blockIdx.x;
    const int pr = blockIdx.y;
    int ti = 0;
    while ((ti + 1) * (ti + 2) / 2 <= pr) ti++;
    const int tj = pr - ti * (ti + 1) / 2;
    const int tx = threadIdx.x & 31, ty = threadIdx.x >> 5;  // 32 x 8
    float* base = out + (size_t)b * (NMAT * NMAT);

    #pragma unroll
    for (int yy = 0; yy < 4; yy++){
        int r = ty + yy * 8;
        s[r][tx] = base[(size_t)(ti * 32 + r) * NMAT + tj * 32 + tx];
    }
    __syncthreads();
    if (ti != tj){
        #pragma unroll
        for (int yy = 0; yy < 4; yy++){
            int r = ty + yy * 8;
            base[(size_t)(tj * 32 + r) * NMAT + ti * 32 + tx] = -s[tx][r];
        }
    } else {
        #pragma unroll
        for (int yy = 0; yy < 4; yy++){
            int r = ty + yy * 8;
            if (tx > r)
                base[(size_t)(ti * 32 + r) * NMAT + ti * 32 + tx] = -s[tx][r];
            else if (tx == r)
                base[(size_t)(ti * 32 + r) * NMAT + ti * 32 + tx] = 0.0f;
        }
    }
}

// -------------------------------------------------------------------------
extern "C" void kernel_launch(void* const* d_in, const int* in_sizes, int n_in,
                              void* d_out, int out_size)
{
    const float* x  = (const float*)d_in[0];   // [1024, 256]
    const float* W1 = (const float*)d_in[1];   // [1024, 256]
    const float* b1 = (const float*)d_in[2];   // [1024]
    const float* W2 = (const float*)d_in[3];   // [32896, 1024]
    const float* b2 = (const float*)d_in[4];   // [32896]
    float* out = (float*)d_out;                // [1024, 256, 256]

    cudaFuncSetAttribute(gemm1_f16, cudaFuncAttributeMaxDynamicSharedMemorySize, G1_SMEM);
    cudaFuncSetAttribute(gemm2_f16, cudaFuncAttributeMaxDynamicSharedMemorySize, G2_SMEM);

    // Convert operands to fp16 in device scratch
    conv_half_k<<<(TRI * HIDW / 4 + 255) / 256, 256>>>((const float4*)W2, TRI * HIDW / 4, 0);
    conv_half_k<<<(BATCH * INW / 4 + 255) / 256, 256>>>((const float4*)x,  BATCH * INW / 4, 1);
    conv_half_k<<<(HIDW * INW / 4 + 255) / 256, 256>>>((const float4*)W1, HIDW * INW / 4, 2);

    // GEMM1: h = softplus(x @ W1^T + b1) -> g_h (fp16)   (M=1024, N=1024, K=256)
    gemm1_f16<<<dim3(8, 8), 256, G1_SMEM>>>(b1);
    // GEMM2: elements = h @ W2^T + b2 -> strict lower triangle of out
    //        (M=1024, N=TRI=255*128, K=1024)
    gemm2_f16<<<dim3(8, 255), 256, G2_SMEM>>>(b2, out);
    // Upper triangle = -lower^T, diagonal = 0
    antisym_kernel<<<dim3(1024, 36), 256>>>(out);
}